// round 16
// baseline (speedup 1.0000x reference)
#include <cuda_runtime.h>
#include <cuda_fp16.h>
#include <stdint.h>
#include <math.h>

#define BB 4096
#define FF 256
#define HH 256
#define MM 3
#define TT 30
#define G3 768
#define IN0 258
#define KP 72
#define KP2 40
#define S0 2
#define S1 2

typedef __half h16;

__device__ h16 g_ctx_hi[BB*FF], g_ctx_lo[BB*FF];
__device__ h16 g_h0[2][MM*BB*HH];
__device__ h16 g_h1[2][MM*BB*HH];
__device__ float g_h0f32[MM*BB*HH];
__device__ float g_h1f[MM*BB*HH];
__device__ h16 g_whh0[MM*G3*HH];
__device__ h16 g_wih1[MM*G3*HH];
__device__ h16 g_whh1[MM*G3*HH];
__device__ h16 g_wc[MM*G3*HH];
__device__ h16 g_gx0h[(size_t)MM*BB*G3];   // fp16, includes b_ih0
__device__ float g_wp0[MM*G3*2];
__device__ float g_dbuf[2][MM*BB*2];
__device__ float g_cum[MM*BB*2];

__device__ __forceinline__ void mma16816(float* d, const uint32_t* a, const uint32_t* b) {
    asm volatile(
        "mma.sync.aligned.m16n8k16.row.col.f32.f16.f16.f32 "
        "{%0,%1,%2,%3}, {%4,%5,%6,%7}, {%8,%9}, {%0,%1,%2,%3};\n"
        : "+f"(d[0]), "+f"(d[1]), "+f"(d[2]), "+f"(d[3])
        : "r"(a[0]), "r"(a[1]), "r"(a[2]), "r"(a[3]), "r"(b[0]), "r"(b[1]));
}
__device__ __forceinline__ void ldsm4(uint32_t* r, const h16* p) {
    uint32_t a = (uint32_t)__cvta_generic_to_shared(p);
    asm volatile("ldmatrix.sync.aligned.m8n8.x4.shared.b16 {%0,%1,%2,%3}, [%4];\n"
                 : "=r"(r[0]), "=r"(r[1]), "=r"(r[2]), "=r"(r[3]) : "r"(a));
}
__device__ __forceinline__ void cpa(h16* s, const h16* g) {
    uint32_t sa = (uint32_t)__cvta_generic_to_shared(s);
    asm volatile("cp.async.cg.shared.global [%0], [%1], 16;\n" :: "r"(sa), "l"(g));
}
#define CP_COMMIT   asm volatile("cp.async.commit_group;\n" ::: "memory")
#define CP_WAITG(n) asm volatile("cp.async.wait_group %0;\n" :: "n"(n) : "memory")

__device__ __forceinline__ void splith(float v, h16& hi, h16& lo) {
    hi = __float2half_rn(v);
    lo = __float2half_rn(v - __half2float(hi));
}
__device__ __forceinline__ float sigf(float x) { return 1.f/(1.f+expf(-x)); }

// ---------- prep ----------
__global__ void k_prep_all(const float* __restrict__ ctx, const float* __restrict__ whh0,
                           const float* __restrict__ wih1, const float* __restrict__ whh1,
                           const float* __restrict__ wih0) {
    const int n1 = MM*G3*HH;
    const int N0 = BB*FF, N1 = N0 + 4*n1, N2 = N1 + MM*G3, N3 = N2 + MM*BB*2;
    for (int i = blockIdx.x*blockDim.x + threadIdx.x; i < N3; i += gridDim.x*blockDim.x) {
        if (i < N0) {
            float v = ctx[i];
            h16 hi, lo; splith(v, hi, lo);
            g_ctx_hi[i] = hi; g_ctx_lo[i] = lo;
#pragma unroll
            for (int m = 0; m < MM; m++) {
                int o = m*BB*HH + i;
                g_h0[0][o] = hi; g_h1[0][o] = hi;
                g_h0f32[o] = v; g_h1f[o] = v;
            }
        } else if (i < N1) {
            int j = i - N0, a = j / n1, e = j - a*n1;
            float v;
            if (a == 3) {
                int m = e / (G3*HH), r = (e - m*G3*HH) / HH, c = e % HH;
                v = wih0[((size_t)m*G3 + r)*IN0 + 2 + c];
            } else v = (a == 0 ? whh0 : (a == 1 ? wih1 : whh1))[e];
            h16 w = __float2half_rn(v);
            if      (a == 0) g_whh0[e] = w;
            else if (a == 1) g_wih1[e] = w;
            else if (a == 2) g_whh1[e] = w;
            else             g_wc[e]   = w;
        } else if (i < N2) {
            int j = i - N1;
            g_wp0[j*2+0] = wih0[(size_t)j*IN0 + 0];
            g_wp0[j*2+1] = wih0[(size_t)j*IN0 + 1];
        } else {
            int j = i - N2;
            g_dbuf[0][j] = 0.f; g_dbuf[1][j] = 0.f; g_cum[j] = 0.f;
        }
    }
}

// ---------- gx0 = ctx @ wc^T + b_ih0 (once, fp16 output) ----------
__global__ void __launch_bounds__(128) k_gx0(const float* __restrict__ bih0) {
    const int m = blockIdx.z, rb = blockIdx.x, ub = blockIdx.y;
    __shared__ __align__(16) h16 sm[(2*64 + 32) * KP];
    h16* As = sm; h16* Ws = sm + 2*64*KP;
    const h16* Ap[2] = { g_ctx_hi, g_ctx_lo };
    const h16* W = g_wc + m*G3*HH;
    const int tid = threadIdx.x, lane = tid & 31, wid = tid >> 5;
    const int wm = wid & 1, wn = wid >> 1, gq = lane >> 2, tg = lane & 3;
    float acc[2][2][4];
#pragma unroll
    for (int a = 0; a < 2; a++)
#pragma unroll
    for (int b = 0; b < 2; b++)
#pragma unroll
    for (int e = 0; e < 4; e++) acc[a][b][e] = 0.f;
    for (int kc = 0; kc < 4; kc++) {
        const int k0 = kc * 64;
        for (int idx = tid; idx < 1024; idx += 128) {
            int t = idx >> 9, rem = idx & 511, r = rem >> 3, c = rem & 7;
            ((uint4*)As)[t*64*9 + r*9 + c] = ((const uint4*)(Ap[t] + (size_t)(rb*64+r)*HH + k0))[c];
        }
        for (int idx = tid; idx < 256; idx += 128) {
            int r = idx >> 3, c = idx & 7;
            ((uint4*)Ws)[r*9 + c] = ((const uint4*)(W + (size_t)(ub*32+r)*HH + k0))[c];
        }
        __syncthreads();
#pragma unroll
        for (int ks = 0; ks < 4; ks++) {
            const int kk = ks * 16;
            uint32_t afr[2][2][4];
#pragma unroll
            for (int hl = 0; hl < 2; hl++)
#pragma unroll
                for (int mf = 0; mf < 2; mf++) {
                    const h16* at = As + hl*64*KP + (wm*32+mf*16+gq)*KP + kk + tg*2;
                    afr[hl][mf][0] = *(const uint32_t*)at;
                    afr[hl][mf][1] = *(const uint32_t*)(at + 8*KP);
                    afr[hl][mf][2] = *(const uint32_t*)(at + 8);
                    afr[hl][mf][3] = *(const uint32_t*)(at + 8*KP + 8);
                }
            uint32_t bfr[2][2];
#pragma unroll
            for (int nf = 0; nf < 2; nf++) {
                const h16* wt = Ws + (wn*16+nf*8+gq)*KP + kk + tg*2;
                bfr[nf][0] = *(const uint32_t*)wt;
                bfr[nf][1] = *(const uint32_t*)(wt + 8);
            }
#pragma unroll
            for (int mf = 0; mf < 2; mf++)
#pragma unroll
                for (int nf = 0; nf < 2; nf++) {
                    mma16816(acc[mf][nf], afr[0][mf], bfr[nf]);
                    mma16816(acc[mf][nf], afr[1][mf], bfr[nf]);
                }
        }
        __syncthreads();
    }
#pragma unroll
    for (int mf = 0; mf < 2; mf++)
#pragma unroll
    for (int e = 0; e < 2; e++) {
        int row = rb*64 + wm*32 + mf*16 + gq + e*8;
#pragma unroll
        for (int nf = 0; nf < 2; nf++)
#pragma unroll
        for (int cc = 0; cc < 2; cc++) {
            int col = ub*32 + wn*16 + nf*8 + tg*2 + cc;
            g_gx0h[((size_t)m*BB+row)*G3 + col] =
                __float2half_rn(acc[mf][nf][e*2+cc] + bih0[m*G3+col]);
        }
    }
}

// ---------- layer0 fused + delta consume/cumsum prologue (4 blocks/SM) ----------
__global__ void __launch_bounds__(256, 4) k_l0(const float* __restrict__ bhh0, int p, int t,
                                               const float* __restrict__ ob,
                                               float* __restrict__ out) {
    const int m = blockIdx.z, rb = blockIdx.x, ub = blockIdx.y, q = p^1;
    extern __shared__ __align__(16) h16 sm0[];
    h16* As = sm0;
    h16* Ws = sm0 + S0*64*KP2;
    __shared__ float s_d[128];
    const h16* A = g_h0[p] + m*BB*HH;
    const h16* W = g_whh0 + m*G3*HH;
    const int tid = threadIdx.x, lane = tid & 31, wid = tid >> 5;
    const int wm = wid >> 1, wn = wid & 1, gq = lane >> 2, tg = lane & 3;
    const int ar = lane & 15, ac = (lane >> 4) * 8;
    const int br = ((lane >> 4) & 1) * 8 + (lane & 7), bc = ((lane >> 3) & 1) * 8;

    float acc[3][2][4];
#pragma unroll
    for (int g = 0; g < 3; g++)
#pragma unroll
    for (int b = 0; b < 2; b++)
#pragma unroll
    for (int e = 0; e < 4; e++) acc[g][b][e] = 0.f;

    auto load = [&](int s, int c) {
        for (int i = tid; i < 256; i += 256) {
            int r = i >> 2, ch = i & 3;
            cpa(As + (s*64 + r)*KP2 + ch*8, A + (size_t)(rb*64 + r)*HH + c*32 + ch*8);
        }
        for (int i = tid; i < 384; i += 256) {
            int g = i >> 7, rem = i & 127, r = rem >> 2, ch = rem & 3;
            cpa(Ws + ((s*3 + g)*32 + r)*KP2 + ch*8,
                W + (size_t)(g*HH + ub*32 + r)*HH + c*32 + ch*8);
        }
    };

#pragma unroll
    for (int s = 0; s < S0-1; s++) { load(s, s); CP_COMMIT; }

    const float* dprev = g_dbuf[(t+1)&1];
    if (tid < 128) {
        int lrow = tid >> 1, c = tid & 1;
        int row = rb*64 + lrow;
        float d = (t > 0) ? (dprev[(m*BB+row)*2+c] + ob[m*2+c]) : 0.f;
        s_d[tid] = d;
        if (ub == 0) {
            g_dbuf[t&1][(m*BB+row)*2+c] = 0.f;
            if (t > 0) {
                float cu = g_cum[(m*BB+row)*2+c] + d;
                g_cum[(m*BB+row)*2+c] = cu;
                out[(((size_t)row*MM + m)*TT + (t-1))*2 + c] = cu;
            }
        }
    }
    __syncthreads();

    for (int c = 0; c < 8; c++) {
        CP_WAITG(S0-2);
        __syncthreads();
        if (c + S0-1 < 8) load((c + S0-1) % S0, c + S0-1);
        CP_COMMIT;
        const int s = c % S0;
#pragma unroll
        for (int ks = 0; ks < 2; ks++) {
            const int kk = ks * 16;
            uint32_t afr[4];
            ldsm4(afr, As + (s*64 + wm*16 + ar)*KP2 + kk + ac);
#pragma unroll
            for (int g = 0; g < 3; g++) {
                uint32_t bfr[4];
                ldsm4(bfr, Ws + ((s*3 + g)*32 + wn*16 + br)*KP2 + kk + bc);
                mma16816(acc[g][0], afr, &bfr[0]);
                mma16816(acc[g][1], afr, &bfr[2]);
            }
        }
    }

    const float* bh = bhh0 + m*G3;
#pragma unroll
    for (int e = 0; e < 2; e++) {
        int lrow = wm*16 + gq + e*8;
        int row = rb*64 + lrow;
        float px = s_d[lrow*2+0], py = s_d[lrow*2+1];
        size_t gxb = (size_t)(m*BB+row)*G3;
#pragma unroll
        for (int nf = 0; nf < 2; nf++)
#pragma unroll
        for (int cc = 0; cc < 2; cc++) {
            int u = ub*32 + wn*16 + nf*8 + tg*2 + cc;
            int ec = e*2+cc;
            const float* w0 = g_wp0 + (m*G3+u)*2;
            const float* w1p = g_wp0 + (m*G3+HH+u)*2;
            const float* w2p = g_wp0 + (m*G3+2*HH+u)*2;
            float xr = __half2float(g_gx0h[gxb+u])      + px*w0[0]  + py*w0[1];
            float xz = __half2float(g_gx0h[gxb+HH+u])   + px*w1p[0] + py*w1p[1];
            float xn = __half2float(g_gx0h[gxb+2*HH+u]) + px*w2p[0] + py*w2p[1];
            float r = sigf(xr + acc[0][nf][ec] + bh[u]);
            float z = sigf(xz + acc[1][nf][ec] + bh[HH+u]);
            float n = tanhf(xn + r*(acc[2][nf][ec] + bh[2*HH+u]));
            size_t hix = (size_t)(m*BB+row)*HH + u;
            float h = (1.f-z)*n + z*g_h0f32[hix];
            g_h0f32[hix] = h;
            g_h0[q][hix] = __float2half_rn(h);
        }
    }
}

// ---------- layer1: 128-row x 64-u tiles, 512 threads, traffic halved ----------
__global__ void __launch_bounds__(512, 1) k_l1(const float* __restrict__ bih1,
                                               const float* __restrict__ bhh1, int p,
                                               const float* __restrict__ ow) {
    const int m = blockIdx.z, rb = blockIdx.x, ub = blockIdx.y, q = p^1;
    extern __shared__ __align__(16) h16 sm1[];
    h16* As = sm1;                        // S1 x 2 x 128 x KP2
    h16* Ws = sm1 + S1*2*128*KP2;         // S1 x 6 x 64 x KP2
    const h16* Ap[2] = { g_h0[q] + m*BB*HH, g_h1[p] + m*BB*HH };
    const h16* Wp[2] = { g_wih1 + m*G3*HH, g_whh1 + m*G3*HH };
    const int tid = threadIdx.x, lane = tid & 31, wid = tid >> 5;
    const int wm = wid >> 1, wn = wid & 1, gq = lane >> 2, tg = lane & 3;
    const int ar = lane & 15, ac = (lane >> 4) * 8;
    const int br = ((lane >> 4) & 1) * 8 + (lane & 7), bc = ((lane >> 3) & 1) * 8;

    float acc[4][4][4];   // r, z, xn, hn x 4 nfrags
#pragma unroll
    for (int a = 0; a < 4; a++)
#pragma unroll
    for (int b = 0; b < 4; b++)
#pragma unroll
    for (int e = 0; e < 4; e++) acc[a][b][e] = 0.f;

    auto load = [&](int s, int c) {
        for (int i = tid; i < 1024; i += 512) {  // A: 2 x 128 x 4
            int t = i >> 9, rem = i & 511, r = rem >> 2, ch = rem & 3;
            cpa(As + ((s*2 + t)*128 + r)*KP2 + ch*8,
                Ap[t] + (size_t)(rb*128 + r)*HH + c*32 + ch*8);
        }
        for (int i = tid; i < 1536; i += 512) {  // W: 6 x 64 x 4
            int t = i >> 8, rem = i & 255, r = rem >> 2, ch = rem & 3;
            int mat = t / 3, g = t % 3;
            cpa(Ws + ((s*6 + t)*64 + r)*KP2 + ch*8,
                Wp[mat] + (size_t)(g*HH + ub*64 + r)*HH + c*32 + ch*8);
        }
    };

#pragma unroll
    for (int s = 0; s < S1-1; s++) { load(s, s); CP_COMMIT; }
    for (int c = 0; c < 8; c++) {
        CP_WAITG(S1-2);
        __syncthreads();
        if (c + S1-1 < 8) load((c + S1-1) % S1, c + S1-1);
        CP_COMMIT;
        const int s = c % S1;
#pragma unroll
        for (int ks = 0; ks < 2; ks++) {
            const int kk = ks * 16;
#pragma unroll
            for (int mat = 0; mat < 2; mat++) {
                uint32_t afr[4];
                ldsm4(afr, As + ((s*2 + mat)*128 + wm*16 + ar)*KP2 + kk + ac);
#pragma unroll
                for (int g = 0; g < 3; g++) {
                    uint32_t bfr[2][4];
                    ldsm4(bfr[0], Ws + ((s*6 + mat*3 + g)*64 + wn*32 + br)*KP2 + kk + bc);
                    ldsm4(bfr[1], Ws + ((s*6 + mat*3 + g)*64 + wn*32 + 16 + br)*KP2 + kk + bc);
                    int type = (g == 2) ? (2 + mat) : g;
#pragma unroll
                    for (int nf = 0; nf < 4; nf++)
                        mma16816(acc[type][nf], afr, &bfr[nf>>1][(nf&1)*2]);
                }
            }
        }
    }

    const float* bi = bih1 + m*G3; const float* bh = bhh1 + m*G3;
    float* dcur = g_dbuf[p&1];
#pragma unroll
    for (int e = 0; e < 2; e++) {
        int row = rb*128 + wm*16 + gq + e*8;
        float pa0 = 0.f, pa1 = 0.f;
#pragma unroll
        for (int nf = 0; nf < 4; nf++)
#pragma unroll
        for (int cc = 0; cc < 2; cc++) {
            int u = ub*64 + wn*32 + nf*8 + tg*2 + cc;
            int ec = e*2+cc;
            float r = sigf(acc[0][nf][ec] + bi[u]      + bh[u]);
            float z = sigf(acc[1][nf][ec] + bi[HH+u]   + bh[HH+u]);
            float n = tanhf(acc[2][nf][ec] + bi[2*HH+u] + r*(acc[3][nf][ec] + bh[2*HH+u]));
            size_t hix = (size_t)(m*BB+row)*HH + u;
            float h = (1.f-z)*n + z*g_h1f[hix];
            g_h1f[hix] = h;
            g_h1[q][hix] = __float2half_rn(h);
            pa0 += h * __ldg(&ow[(m*2+0)*HH + u]);
            pa1 += h * __ldg(&ow[(m*2+1)*HH + u]);
        }
        pa0 += __shfl_xor_sync(0xffffffffu, pa0, 1);
        pa0 += __shfl_xor_sync(0xffffffffu, pa0, 2);
        pa1 += __shfl_xor_sync(0xffffffffu, pa1, 1);
        pa1 += __shfl_xor_sync(0xffffffffu, pa1, 2);
        if (tg == 0) {
            atomicAdd(&dcur[(m*BB+row)*2+0], pa0);
            atomicAdd(&dcur[(m*BB+row)*2+1], pa1);
        }
    }
}

// ---------- final-step cumsum + output ----------
__global__ void k_tail(const float* __restrict__ ob, float* __restrict__ out) {
    int idx = blockIdx.x*256 + threadIdx.x;
    if (idx >= MM*BB*2) return;
    int c = idx & 1, mr = idx >> 1;
    int m = mr >> 12, row = mr & (BB-1);
    float cu = g_cum[idx] + g_dbuf[(TT-1)&1][idx] + ob[m*2+c];
    out[(((size_t)row*MM + m)*TT + (TT-1))*2 + c] = cu;
}

// ---------- mode probs ----------
__global__ void k_modeprobs(const float* __restrict__ ctx,
                            const float* __restrict__ w1, const float* __restrict__ b1,
                            const float* __restrict__ w2, const float* __restrict__ b2,
                            float* __restrict__ probs) {
    int gw = (blockIdx.x * blockDim.x + threadIdx.x) >> 5;
    int lane = threadIdx.x & 31;
    int b0 = gw * 4;
    if (b0 >= BB) return;
    int u0 = lane * 2, u1 = u0 + 1;
    float acc[4][2];
#pragma unroll
    for (int r = 0; r < 4; r++) { acc[r][0] = 0.f; acc[r][1] = 0.f; }
    for (int k = 0; k < FF; k++) {
        float wa = __ldg(&w1[u0*FF+k]), wb = __ldg(&w1[u1*FF+k]);
#pragma unroll
        for (int r = 0; r < 4; r++) {
            float c = __ldg(&ctx[(size_t)(b0+r)*FF+k]);
            acc[r][0] += c*wa; acc[r][1] += c*wb;
        }
    }
#pragma unroll
    for (int r = 0; r < 4; r++) {
        float h0v = fmaxf(acc[r][0] + b1[u0], 0.f);
        float h1v = fmaxf(acc[r][1] + b1[u1], 0.f);
        float lg[3];
#pragma unroll
        for (int m = 0; m < 3; m++) {
            float pp = h0v*w2[m*64+u0] + h1v*w2[m*64+u1];
#pragma unroll
            for (int o = 16; o; o >>= 1) pp += __shfl_xor_sync(0xffffffffu, pp, o);
            lg[m] = pp + b2[m];
        }
        if (lane == 0) {
            float mx = fmaxf(lg[0], fmaxf(lg[1], lg[2]));
            float e0 = expf(lg[0]-mx), e1 = expf(lg[1]-mx), e2 = expf(lg[2]-mx);
            float s = e0+e1+e2;
            probs[(size_t)(b0+r)*MM+0] = e0/s;
            probs[(size_t)(b0+r)*MM+1] = e1/s;
            probs[(size_t)(b0+r)*MM+2] = e2/s;
        }
    }
}

extern "C" void kernel_launch(void* const* d_in, const int* in_sizes, int n_in,
                              void* d_out, int out_size) {
    const float* ctx  = (const float*)d_in[0];
    const float* wih0 = (const float*)d_in[5];
    const float* bih0 = (const float*)d_in[7];
    const float* bhh0 = (const float*)d_in[8];
    const float* bih1 = (const float*)d_in[11];
    const float* bhh1 = (const float*)d_in[12];
    const float* ow   = (const float*)d_in[13];
    const float* ob   = (const float*)d_in[14];
    float* out = (float*)d_out;
    float* probs = out + (size_t)BB*MM*TT*2;

    const int SM_L0 = (S0*64 + S0*3*32) * KP2 * (int)sizeof(h16);      // 25600
    const int SM_L1 = (S1*2*128 + S1*6*64) * KP2 * (int)sizeof(h16);   // 102400
    cudaFuncSetAttribute(k_l0, cudaFuncAttributeMaxDynamicSharedMemorySize, SM_L0);
    cudaFuncSetAttribute(k_l1, cudaFuncAttributeMaxDynamicSharedMemorySize, SM_L1);

    const int NPREP = BB*FF + 4*MM*G3*HH + MM*G3 + MM*BB*2;
    k_prep_all<<<(NPREP+255)/256, 256>>>(ctx, (const float*)d_in[6], (const float*)d_in[9],
                                         (const float*)d_in[10], wih0);

    dim3 g0(BB/64, G3/32, MM);
    k_gx0<<<g0, 128>>>(bih0);

    dim3 gl0(BB/64, HH/32, MM);
    dim3 gl1(BB/128, HH/64, MM);
    for (int t = 0; t < TT; t++) {
        int p = t & 1;
        k_l0<<<gl0, 256, SM_L0>>>(bhh0, p, t, ob, out);
        k_l1<<<gl1, 512, SM_L1>>>(bih1, bhh1, p, ow);
    }
    k_tail<<<(MM*BB*2+255)/256, 256>>>(ob, out);

    k_modeprobs<<<256, 128>>>(ctx, (const float*)d_in[1], (const float*)d_in[2],
                              (const float*)d_in[3], (const float*)d_in[4], probs);
}

// round 17
// speedup vs baseline: 1.0812x; 1.0812x over previous
#include <cuda_runtime.h>
#include <cuda_fp16.h>
#include <stdint.h>
#include <math.h>

#define BB 4096
#define FF 256
#define HH 256
#define MM 3
#define TT 30
#define G3 768
#define IN0 258
#define KP 72
#define KP2 40
#define S0 4
#define S1 2

typedef __half h16;

__device__ h16 g_ctx[BB*FF];
__device__ h16 g_h0[2][MM*BB*HH];
__device__ h16 g_h1[2][MM*BB*HH];
__device__ float g_h0f32[MM*BB*HH];
__device__ float g_h1f[MM*BB*HH];
__device__ h16 g_whh0[MM*G3*HH];
__device__ h16 g_wih1[MM*G3*HH];
__device__ h16 g_whh1[MM*G3*HH];
__device__ h16 g_wc[MM*G3*HH];
__device__ h16 g_gx0h[(size_t)MM*BB*G3];   // fp16, includes b_ih0
__device__ float g_wp0[MM*G3*2];
__device__ float g_dbuf[2][MM*BB*2];
__device__ float g_cum[MM*BB*2];

__device__ __forceinline__ void mma16816(float* d, const uint32_t* a, const uint32_t* b) {
    asm volatile(
        "mma.sync.aligned.m16n8k16.row.col.f32.f16.f16.f32 "
        "{%0,%1,%2,%3}, {%4,%5,%6,%7}, {%8,%9}, {%0,%1,%2,%3};\n"
        : "+f"(d[0]), "+f"(d[1]), "+f"(d[2]), "+f"(d[3])
        : "r"(a[0]), "r"(a[1]), "r"(a[2]), "r"(a[3]), "r"(b[0]), "r"(b[1]));
}
__device__ __forceinline__ void ldsm4(uint32_t* r, const h16* p) {
    uint32_t a = (uint32_t)__cvta_generic_to_shared(p);
    asm volatile("ldmatrix.sync.aligned.m8n8.x4.shared.b16 {%0,%1,%2,%3}, [%4];\n"
                 : "=r"(r[0]), "=r"(r[1]), "=r"(r[2]), "=r"(r[3]) : "r"(a));
}
__device__ __forceinline__ void cpa(h16* s, const h16* g) {
    uint32_t sa = (uint32_t)__cvta_generic_to_shared(s);
    asm volatile("cp.async.cg.shared.global [%0], [%1], 16;\n" :: "r"(sa), "l"(g));
}
#define CP_COMMIT   asm volatile("cp.async.commit_group;\n" ::: "memory")
#define CP_WAITG(n) asm volatile("cp.async.wait_group %0;\n" :: "n"(n) : "memory")

__device__ __forceinline__ float sigf(float x) { return 1.f/(1.f+expf(-x)); }

// ---------- prep ----------
__global__ void k_prep_all(const float* __restrict__ ctx, const float* __restrict__ whh0,
                           const float* __restrict__ wih1, const float* __restrict__ whh1,
                           const float* __restrict__ wih0) {
    const int n1 = MM*G3*HH;
    const int N0 = BB*FF, N1 = N0 + 4*n1, N2 = N1 + MM*G3, N3 = N2 + MM*BB*2;
    for (int i = blockIdx.x*blockDim.x + threadIdx.x; i < N3; i += gridDim.x*blockDim.x) {
        if (i < N0) {
            float v = ctx[i];
            h16 hv = __float2half_rn(v);
            g_ctx[i] = hv;
#pragma unroll
            for (int m = 0; m < MM; m++) {
                int o = m*BB*HH + i;
                g_h0[0][o] = hv; g_h1[0][o] = hv;
                g_h0f32[o] = v; g_h1f[o] = v;
            }
        } else if (i < N1) {
            int j = i - N0, a = j / n1, e = j - a*n1;
            float v;
            if (a == 3) {
                int m = e / (G3*HH), r = (e - m*G3*HH) / HH, c = e % HH;
                v = wih0[((size_t)m*G3 + r)*IN0 + 2 + c];
            } else v = (a == 0 ? whh0 : (a == 1 ? wih1 : whh1))[e];
            h16 w = __float2half_rn(v);
            if      (a == 0) g_whh0[e] = w;
            else if (a == 1) g_wih1[e] = w;
            else if (a == 2) g_whh1[e] = w;
            else             g_wc[e]   = w;
        } else if (i < N2) {
            int j = i - N1;
            g_wp0[j*2+0] = wih0[(size_t)j*IN0 + 0];
            g_wp0[j*2+1] = wih0[(size_t)j*IN0 + 1];
        } else {
            int j = i - N2;
            g_dbuf[0][j] = 0.f; g_dbuf[1][j] = 0.f; g_cum[j] = 0.f;
        }
    }
}

// ---------- gx0 = ctx @ wc^T + b_ih0 (once, fp16 in/out, single-precision A) ----------
__global__ void __launch_bounds__(128) k_gx0(const float* __restrict__ bih0) {
    const int m = blockIdx.z, rb = blockIdx.x, ub = blockIdx.y;
    __shared__ __align__(16) h16 sm[(64 + 32) * KP];
    h16* As = sm; h16* Ws = sm + 64*KP;
    const h16* W = g_wc + m*G3*HH;
    const int tid = threadIdx.x, lane = tid & 31, wid = tid >> 5;
    const int wm = wid & 1, wn = wid >> 1, gq = lane >> 2, tg = lane & 3;
    float acc[2][2][4];
#pragma unroll
    for (int a = 0; a < 2; a++)
#pragma unroll
    for (int b = 0; b < 2; b++)
#pragma unroll
    for (int e = 0; e < 4; e++) acc[a][b][e] = 0.f;
    for (int kc = 0; kc < 4; kc++) {
        const int k0 = kc * 64;
        for (int idx = tid; idx < 512; idx += 128) {
            int r = idx >> 3, c = idx & 7;
            ((uint4*)As)[r*9 + c] = ((const uint4*)(g_ctx + (size_t)(rb*64+r)*HH + k0))[c];
        }
        for (int idx = tid; idx < 256; idx += 128) {
            int r = idx >> 3, c = idx & 7;
            ((uint4*)Ws)[r*9 + c] = ((const uint4*)(W + (size_t)(ub*32+r)*HH + k0))[c];
        }
        __syncthreads();
#pragma unroll
        for (int ks = 0; ks < 4; ks++) {
            const int kk = ks * 16;
            uint32_t afr[2][4];
#pragma unroll
            for (int mf = 0; mf < 2; mf++) {
                const h16* at = As + (wm*32+mf*16+gq)*KP + kk + tg*2;
                afr[mf][0] = *(const uint32_t*)at;
                afr[mf][1] = *(const uint32_t*)(at + 8*KP);
                afr[mf][2] = *(const uint32_t*)(at + 8);
                afr[mf][3] = *(const uint32_t*)(at + 8*KP + 8);
            }
            uint32_t bfr[2][2];
#pragma unroll
            for (int nf = 0; nf < 2; nf++) {
                const h16* wt = Ws + (wn*16+nf*8+gq)*KP + kk + tg*2;
                bfr[nf][0] = *(const uint32_t*)wt;
                bfr[nf][1] = *(const uint32_t*)(wt + 8);
            }
#pragma unroll
            for (int mf = 0; mf < 2; mf++)
#pragma unroll
                for (int nf = 0; nf < 2; nf++)
                    mma16816(acc[mf][nf], afr[mf], bfr[nf]);
        }
        __syncthreads();
    }
#pragma unroll
    for (int mf = 0; mf < 2; mf++)
#pragma unroll
    for (int e = 0; e < 2; e++) {
        int row = rb*64 + wm*32 + mf*16 + gq + e*8;
#pragma unroll
        for (int nf = 0; nf < 2; nf++)
#pragma unroll
        for (int cc = 0; cc < 2; cc++) {
            int col = ub*32 + wn*16 + nf*8 + tg*2 + cc;
            g_gx0h[((size_t)m*BB+row)*G3 + col] =
                __float2half_rn(acc[mf][nf][e*2+cc] + bih0[m*G3+col]);
        }
    }
}

// ---------- layer0 fused + delta consume/cumsum prologue (3 blocks/SM) ----------
__global__ void __launch_bounds__(256, 3) k_l0(const float* __restrict__ bhh0, int p, int t,
                                               const float* __restrict__ ob,
                                               float* __restrict__ out) {
    const int m = blockIdx.z, rb = blockIdx.x, ub = blockIdx.y, q = p^1;
    extern __shared__ __align__(16) h16 sm0[];
    h16* As = sm0;
    h16* Ws = sm0 + S0*64*KP2;
    __shared__ float s_d[128];
    const h16* A = g_h0[p] + m*BB*HH;
    const h16* W = g_whh0 + m*G3*HH;
    const int tid = threadIdx.x, lane = tid & 31, wid = tid >> 5;
    const int wm = wid >> 1, wn = wid & 1, gq = lane >> 2, tg = lane & 3;
    const int ar = lane & 15, ac = (lane >> 4) * 8;
    const int br = ((lane >> 4) & 1) * 8 + (lane & 7), bc = ((lane >> 3) & 1) * 8;

    float acc[3][2][4];
#pragma unroll
    for (int g = 0; g < 3; g++)
#pragma unroll
    for (int b = 0; b < 2; b++)
#pragma unroll
    for (int e = 0; e < 4; e++) acc[g][b][e] = 0.f;

    auto load = [&](int s, int c) {
        for (int i = tid; i < 256; i += 256) {
            int r = i >> 2, ch = i & 3;
            cpa(As + (s*64 + r)*KP2 + ch*8, A + (size_t)(rb*64 + r)*HH + c*32 + ch*8);
        }
        for (int i = tid; i < 384; i += 256) {
            int g = i >> 7, rem = i & 127, r = rem >> 2, ch = rem & 3;
            cpa(Ws + ((s*3 + g)*32 + r)*KP2 + ch*8,
                W + (size_t)(g*HH + ub*32 + r)*HH + c*32 + ch*8);
        }
    };

#pragma unroll
    for (int s = 0; s < S0-1; s++) { load(s, s); CP_COMMIT; }

    const float* dprev = g_dbuf[(t+1)&1];
    if (tid < 128) {
        int lrow = tid >> 1, c = tid & 1;
        int row = rb*64 + lrow;
        float d = (t > 0) ? (dprev[(m*BB+row)*2+c] + ob[m*2+c]) : 0.f;
        s_d[tid] = d;
        if (ub == 0) {
            g_dbuf[t&1][(m*BB+row)*2+c] = 0.f;
            if (t > 0) {
                float cu = g_cum[(m*BB+row)*2+c] + d;
                g_cum[(m*BB+row)*2+c] = cu;
                out[(((size_t)row*MM + m)*TT + (t-1))*2 + c] = cu;
            }
        }
    }
    __syncthreads();

    for (int c = 0; c < 8; c++) {
        CP_WAITG(S0-2);
        __syncthreads();
        if (c + S0-1 < 8) load((c + S0-1) % S0, c + S0-1);
        CP_COMMIT;
        const int s = c % S0;
#pragma unroll
        for (int ks = 0; ks < 2; ks++) {
            const int kk = ks * 16;
            uint32_t afr[4];
            ldsm4(afr, As + (s*64 + wm*16 + ar)*KP2 + kk + ac);
#pragma unroll
            for (int g = 0; g < 3; g++) {
                uint32_t bfr[4];
                ldsm4(bfr, Ws + ((s*3 + g)*32 + wn*16 + br)*KP2 + kk + bc);
                mma16816(acc[g][0], afr, &bfr[0]);
                mma16816(acc[g][1], afr, &bfr[2]);
            }
        }
    }

    const float* bh = bhh0 + m*G3;
#pragma unroll
    for (int e = 0; e < 2; e++) {
        int lrow = wm*16 + gq + e*8;
        int row = rb*64 + lrow;
        float px = s_d[lrow*2+0], py = s_d[lrow*2+1];
        size_t gxb = (size_t)(m*BB+row)*G3;
#pragma unroll
        for (int nf = 0; nf < 2; nf++)
#pragma unroll
        for (int cc = 0; cc < 2; cc++) {
            int u = ub*32 + wn*16 + nf*8 + tg*2 + cc;
            int ec = e*2+cc;
            const float* w0 = g_wp0 + (m*G3+u)*2;
            const float* w1p = g_wp0 + (m*G3+HH+u)*2;
            const float* w2p = g_wp0 + (m*G3+2*HH+u)*2;
            float xr = __half2float(g_gx0h[gxb+u])      + px*w0[0]  + py*w0[1];
            float xz = __half2float(g_gx0h[gxb+HH+u])   + px*w1p[0] + py*w1p[1];
            float xn = __half2float(g_gx0h[gxb+2*HH+u]) + px*w2p[0] + py*w2p[1];
            float r = sigf(xr + acc[0][nf][ec] + bh[u]);
            float z = sigf(xz + acc[1][nf][ec] + bh[HH+u]);
            float n = tanhf(xn + r*(acc[2][nf][ec] + bh[2*HH+u]));
            size_t hix = (size_t)(m*BB+row)*HH + u;
            float h = (1.f-z)*n + z*g_h0f32[hix];
            g_h0f32[hix] = h;
            g_h0[q][hix] = __float2half_rn(h);
        }
    }
}

// ---------- layer1 fused: r/z shared accumulators, 3 blocks/SM ----------
__global__ void __launch_bounds__(256, 3) k_l1(const float* __restrict__ bih1,
                                               const float* __restrict__ bhh1, int p,
                                               const float* __restrict__ ow) {
    const int m = blockIdx.z, rb = blockIdx.x, ub = blockIdx.y, q = p^1;
    extern __shared__ __align__(16) h16 sm1[];
    h16* As = sm1;                        // S1 x 2 x 64 x KP2
    h16* Ws = sm1 + S1*2*64*KP2;          // S1 x 6 x 32 x KP2
    const h16* Ap[2] = { g_h0[q] + m*BB*HH, g_h1[p] + m*BB*HH };
    const h16* Wp[2] = { g_wih1 + m*G3*HH, g_whh1 + m*G3*HH };
    const int tid = threadIdx.x, lane = tid & 31, wid = tid >> 5;
    const int wm = wid >> 1, wn = wid & 1, gq = lane >> 2, tg = lane & 3;
    const int ar = lane & 15, ac = (lane >> 4) * 8;
    const int br = ((lane >> 4) & 1) * 8 + (lane & 7), bc = ((lane >> 3) & 1) * 8;

    float acc[4][2][4];   // r, z, xn, hn
#pragma unroll
    for (int a = 0; a < 4; a++)
#pragma unroll
    for (int b = 0; b < 2; b++)
#pragma unroll
    for (int e = 0; e < 4; e++) acc[a][b][e] = 0.f;

    auto load = [&](int s, int c) {
        for (int i = tid; i < 512; i += 256) {   // A: 2 x 64 x 4
            int t = i >> 8, rem = i & 255, r = rem >> 2, ch = rem & 3;
            cpa(As + ((s*2 + t)*64 + r)*KP2 + ch*8,
                Ap[t] + (size_t)(rb*64 + r)*HH + c*32 + ch*8);
        }
        for (int i = tid; i < 768; i += 256) {   // W: 6 x 32 x 4
            int t = i >> 7, rem = i & 127, r = rem >> 2, ch = rem & 3;
            int mat = t / 3, g = t % 3;
            cpa(Ws + ((s*6 + t)*32 + r)*KP2 + ch*8,
                Wp[mat] + (size_t)(g*HH + ub*32 + r)*HH + c*32 + ch*8);
        }
    };

#pragma unroll
    for (int s = 0; s < S1-1; s++) { load(s, s); CP_COMMIT; }
    for (int c = 0; c < 8; c++) {
        CP_WAITG(S1-2);
        __syncthreads();
        if (c + S1-1 < 8) load((c + S1-1) % S1, c + S1-1);
        CP_COMMIT;
        const int s = c % S1;
#pragma unroll
        for (int ks = 0; ks < 2; ks++) {
            const int kk = ks * 16;
#pragma unroll
            for (int mat = 0; mat < 2; mat++) {
                uint32_t afr[4];
                ldsm4(afr, As + ((s*2 + mat)*64 + wm*16 + ar)*KP2 + kk + ac);
#pragma unroll
                for (int g = 0; g < 3; g++) {
                    uint32_t bfr[4];
                    ldsm4(bfr, Ws + ((s*6 + mat*3 + g)*32 + wn*16 + br)*KP2 + kk + bc);
                    int type = (g == 2) ? (2 + mat) : g;   // r,z shared; xn=2, hn=3
                    mma16816(acc[type][0], afr, &bfr[0]);
                    mma16816(acc[type][1], afr, &bfr[2]);
                }
            }
        }
    }

    const float* bi = bih1 + m*G3; const float* bh = bhh1 + m*G3;
    float* dcur = g_dbuf[p&1];
#pragma unroll
    for (int e = 0; e < 2; e++) {
        int row = rb*64 + wm*16 + gq + e*8;
        float pa0 = 0.f, pa1 = 0.f;
#pragma unroll
        for (int nf = 0; nf < 2; nf++)
#pragma unroll
        for (int cc = 0; cc < 2; cc++) {
            int u = ub*32 + wn*16 + nf*8 + tg*2 + cc;
            int ec = e*2+cc;
            float r = sigf(acc[0][nf][ec] + bi[u]      + bh[u]);
            float z = sigf(acc[1][nf][ec] + bi[HH+u]   + bh[HH+u]);
            float n = tanhf(acc[2][nf][ec] + bi[2*HH+u] + r*(acc[3][nf][ec] + bh[2*HH+u]));
            size_t hix = (size_t)(m*BB+row)*HH + u;
            float h = (1.f-z)*n + z*g_h1f[hix];
            g_h1f[hix] = h;
            g_h1[q][hix] = __float2half_rn(h);
            pa0 += h * __ldg(&ow[(m*2+0)*HH + u]);
            pa1 += h * __ldg(&ow[(m*2+1)*HH + u]);
        }
        pa0 += __shfl_xor_sync(0xffffffffu, pa0, 1);
        pa0 += __shfl_xor_sync(0xffffffffu, pa0, 2);
        pa1 += __shfl_xor_sync(0xffffffffu, pa1, 1);
        pa1 += __shfl_xor_sync(0xffffffffu, pa1, 2);
        if (tg == 0) {
            atomicAdd(&dcur[(m*BB+row)*2+0], pa0);
            atomicAdd(&dcur[(m*BB+row)*2+1], pa1);
        }
    }
}

// ---------- final-step cumsum + output ----------
__global__ void k_tail(const float* __restrict__ ob, float* __restrict__ out) {
    int idx = blockIdx.x*256 + threadIdx.x;
    if (idx >= MM*BB*2) return;
    int c = idx & 1, mr = idx >> 1;
    int m = mr >> 12, row = mr & (BB-1);
    float cu = g_cum[idx] + g_dbuf[(TT-1)&1][idx] + ob[m*2+c];
    out[(((size_t)row*MM + m)*TT + (TT-1))*2 + c] = cu;
}

// ---------- mode probs ----------
__global__ void k_modeprobs(const float* __restrict__ ctx,
                            const float* __restrict__ w1, const float* __restrict__ b1,
                            const float* __restrict__ w2, const float* __restrict__ b2,
                            float* __restrict__ probs) {
    int gw = (blockIdx.x * blockDim.x + threadIdx.x) >> 5;
    int lane = threadIdx.x & 31;
    int b0 = gw * 4;
    if (b0 >= BB) return;
    int u0 = lane * 2, u1 = u0 + 1;
    float acc[4][2];
#pragma unroll
    for (int r = 0; r < 4; r++) { acc[r][0] = 0.f; acc[r][1] = 0.f; }
    for (int k = 0; k < FF; k++) {
        float wa = __ldg(&w1[u0*FF+k]), wb = __ldg(&w1[u1*FF+k]);
#pragma unroll
        for (int r = 0; r < 4; r++) {
            float c = __ldg(&ctx[(size_t)(b0+r)*FF+k]);
            acc[r][0] += c*wa; acc[r][1] += c*wb;
        }
    }
#pragma unroll
    for (int r = 0; r < 4; r++) {
        float h0v = fmaxf(acc[r][0] + b1[u0], 0.f);
        float h1v = fmaxf(acc[r][1] + b1[u1], 0.f);
        float lg[3];
#pragma unroll
        for (int m = 0; m < 3; m++) {
            float pp = h0v*w2[m*64+u0] + h1v*w2[m*64+u1];
#pragma unroll
            for (int o = 16; o; o >>= 1) pp += __shfl_xor_sync(0xffffffffu, pp, o);
            lg[m] = pp + b2[m];
        }
        if (lane == 0) {
            float mx = fmaxf(lg[0], fmaxf(lg[1], lg[2]));
            float e0 = expf(lg[0]-mx), e1 = expf(lg[1]-mx), e2 = expf(lg[2]-mx);
            float s = e0+e1+e2;
            probs[(size_t)(b0+r)*MM+0] = e0/s;
            probs[(size_t)(b0+r)*MM+1] = e1/s;
            probs[(size_t)(b0+r)*MM+2] = e2/s;
        }
    }
}

extern "C" void kernel_launch(void* const* d_in, const int* in_sizes, int n_in,
                              void* d_out, int out_size) {
    const float* ctx  = (const float*)d_in[0];
    const float* wih0 = (const float*)d_in[5];
    const float* bih0 = (const float*)d_in[7];
    const float* bhh0 = (const float*)d_in[8];
    const float* bih1 = (const float*)d_in[11];
    const float* bhh1 = (const float*)d_in[12];
    const float* ow   = (const float*)d_in[13];
    const float* ob   = (const float*)d_in[14];
    float* out = (float*)d_out;
    float* probs = out + (size_t)BB*MM*TT*2;

    const int SM_L0 = (S0*64 + S0*3*32) * KP2 * (int)sizeof(h16);     // 51200
    const int SM_L1 = (S1*2*64 + S1*6*32) * KP2 * (int)sizeof(h16);   // 51200
    cudaFuncSetAttribute(k_l0, cudaFuncAttributeMaxDynamicSharedMemorySize, SM_L0);
    cudaFuncSetAttribute(k_l1, cudaFuncAttributeMaxDynamicSharedMemorySize, SM_L1);

    const int NPREP = BB*FF + 4*MM*G3*HH + MM*G3 + MM*BB*2;
    k_prep_all<<<(NPREP+255)/256, 256>>>(ctx, (const float*)d_in[6], (const float*)d_in[9],
                                         (const float*)d_in[10], wih0);

    dim3 g0(BB/64, G3/32, MM);
    k_gx0<<<g0, 128>>>(bih0);

    dim3 gl(BB/64, HH/32, MM);
    for (int t = 0; t < TT; t++) {
        int p = t & 1;
        k_l0<<<gl, 256, SM_L0>>>(bhh0, p, t, ob, out);
        k_l1<<<gl, 256, SM_L1>>>(bih1, bhh1, p, ow);
    }
    k_tail<<<(MM*BB*2+255)/256, 256>>>(ob, out);

    k_modeprobs<<<256, 128>>>(ctx, (const float*)d_in[1], (const float*)d_in[2],
                              (const float*)d_in[3], (const float*)d_in[4], probs);
}